// round 11
// baseline (speedup 1.0000x reference)
#include <cuda_runtime.h>
#include <cuda_bf16.h>
#include <cstdint>

#define MTILE 64
#define NREL   7429          // deg>=1 tiles
#define NGEMM  7820
#define G0     597           // gathers scheduled before first gemm pair
#define D0     391           // deg0 tiles
#define NTOTAL 15249         // G0 + D0 + 2*6832 + 597

struct AdjPtrs { const int* p[10]; };

__device__ __align__(1024) unsigned char g_Wh[11][8][8192];
__device__ __align__(1024) unsigned char g_Wl[11][8][8192];
__device__ float g_bias[11][128];
__device__ __align__(1024) unsigned char g_RelHi[(size_t)NREL * 16384];
__device__ __align__(1024) unsigned char g_RelLo[(size_t)NREL * 16384];
__device__ int g_done[NREL];

__device__ __forceinline__ uint32_t smem_u32(const void* p) {
    uint32_t a;
    asm("{ .reg .u64 t; cvta.to.shared.u64 t, %1; cvt.u32.u64 %0, t; }" : "=r"(a) : "l"(p));
    return a;
}
__device__ __forceinline__ void ldsm4(uint32_t* r, uint32_t a) {
    asm volatile("ldmatrix.sync.aligned.m8n8.x4.shared.b16 {%0,%1,%2,%3}, [%4];"
        : "=r"(r[0]), "=r"(r[1]), "=r"(r[2]), "=r"(r[3]) : "r"(a));
}
__device__ __forceinline__ void ldsm4t(uint32_t* r, uint32_t a) {
    asm volatile("ldmatrix.sync.aligned.m8n8.x4.trans.shared.b16 {%0,%1,%2,%3}, [%4];"
        : "=r"(r[0]), "=r"(r[1]), "=r"(r[2]), "=r"(r[3]) : "r"(a));
}
__device__ __forceinline__ void mma16816(float* c, const uint32_t* a, uint32_t b0, uint32_t b1) {
    asm volatile("mma.sync.aligned.m16n8k16.row.col.f32.bf16.bf16.f32 "
        "{%0,%1,%2,%3}, {%4,%5,%6,%7}, {%8,%9}, {%0,%1,%2,%3};"
        : "+f"(c[0]), "+f"(c[1]), "+f"(c[2]), "+f"(c[3])
        : "r"(a[0]), "r"(a[1]), "r"(a[2]), "r"(a[3]), "r"(b0), "r"(b1));
}
__device__ __forceinline__ void cpasync16(uint32_t dst, const void* src) {
    asm volatile("cp.async.cg.shared.global [%0], [%1], 16;" :: "r"(dst), "l"(src) : "memory");
}
#define CP_COMMIT() asm volatile("cp.async.commit_group;" ::: "memory")
#define CP_WAIT1()  asm volatile("cp.async.wait_group 1;" ::: "memory")
#define CP_WAIT0()  asm volatile("cp.async.wait_group 0;" ::: "memory")

__device__ __forceinline__ unsigned long long pack4bf(float a0, float a1, float a2, float a3) {
    __nv_bfloat162 p0 = __floats2bfloat162_rn(a0, a1);
    __nv_bfloat162 p1 = __floats2bfloat162_rn(a2, a3);
    unsigned int u0 = *(unsigned int*)&p0;
    unsigned int u1 = *(unsigned int*)&p1;
    return (unsigned long long)u0 | ((unsigned long long)u1 << 32);
}

// ---------------- weight prep ----------------
__global__ void prep_weights(const float* __restrict__ W0,   const float* __restrict__ b0,
                             const float* __restrict__ Wrel, const float* __restrict__ brel,
                             const float* __restrict__ Wself,const float* __restrict__ bself)
{
    int idx = blockIdx.x * blockDim.x + threadIdx.x;
    if (idx >= 11 * 256 * 128) return;
    int n = idx & 127;
    int k = (idx >> 7) & 255;
    int s = idx >> 15;
    float w;
    if (s == 0) w = (k < 128) ? 0.f : W0[(size_t)(k - 128) * 128 + n];
    else        w = (k < 128) ? Wrel[((size_t)(s - 1) * 128 + k) * 128 + n]
                              : Wself[((size_t)(s - 1) * 128 + (k - 128)) * 128 + n];
    __nv_bfloat16 hi = __float2bfloat16(w);
    __nv_bfloat16 lo = __float2bfloat16(w - __bfloat162float(hi));
    int b = (((k & 31) * 256) + n * 2) ^ ((k & 7) << 4);
    *(__nv_bfloat16*)(g_Wh[s][k >> 5] + b) = hi;
    *(__nv_bfloat16*)(g_Wl[s][k >> 5] + b) = lo;
    if (k == 0) g_bias[s][n] = (s == 0) ? b0[n] : brel[(s - 1) * 128 + n] + bself[(s - 1) * 128 + n];
}

__global__ void reset_done() {
    int i = blockIdx.x * blockDim.x + threadIdx.x;
    if (i < NREL) g_done[i] = 0;
}

// ---------------- gather: rel means -> pre-swizzled bf16 hi/lo images --------
template<int DEG>
__device__ __forceinline__ void gmean(const float* __restrict__ af,
                                      const int* __restrict__ adjp,
                                      unsigned char* __restrict__ dstHi,
                                      unsigned char* __restrict__ dstLo,
                                      int rows, int wrp, int lane)
{
    const int k0 = lane * 4;
    constexpr int UN = (DEG <= 2) ? 4 : (DEG <= 5 ? 2 : 1);
    #pragma unroll 1
    for (int ii = 0; ii < 8; ii += UN) {
        float4 nb[UN][DEG];
        #pragma unroll
        for (int u = 0; u < UN; ++u) {
            int m = wrp * 8 + ii + u;
            int ml = (m < rows) ? m : 0;
            int idxs[DEG];
            const int* ar = adjp + (size_t)ml * DEG;
            #pragma unroll
            for (int j = 0; j < DEG; ++j) idxs[j] = __ldg(ar + j);
            #pragma unroll
            for (int j = 0; j < DEG; ++j)
                nb[u][j] = *(const float4*)(af + (size_t)idxs[j] * 128 + k0);
        }
        #pragma unroll
        for (int u = 0; u < UN; ++u) {
            int m = wrp * 8 + ii + u;
            if (m >= rows) continue;
            float4 r4 = make_float4(0.f, 0.f, 0.f, 0.f);
            #pragma unroll
            for (int j = 0; j < DEG; ++j) {
                r4.x += nb[u][j].x; r4.y += nb[u][j].y;
                r4.z += nb[u][j].z; r4.w += nb[u][j].w;
            }
            constexpr float inv = 1.0f / (float)DEG;
            r4.x *= inv; r4.y *= inv; r4.z *= inv; r4.w *= inv;
            float rh0 = __bfloat162float(__float2bfloat16(r4.x));
            float rh1 = __bfloat162float(__float2bfloat16(r4.y));
            float rh2 = __bfloat162float(__float2bfloat16(r4.z));
            float rh3 = __bfloat162float(__float2bfloat16(r4.w));
            int off = ((m * 256 + 8 * lane) ^ ((m & 7) << 4));
            *(unsigned long long*)(dstHi + off) = pack4bf(r4.x, r4.y, r4.z, r4.w);
            *(unsigned long long*)(dstLo + off) = pack4bf(r4.x - rh0, r4.y - rh1, r4.z - rh2, r4.w - rh3);
        }
    }
}

// ---------------- mixed kernel: interleaved gather + gemm CTAs ----------------
__global__ __launch_bounds__(256, 2)
void graphconv_mix(const float* __restrict__ af, AdjPtrs adj, float* __restrict__ out)
{
    const int tid  = threadIdx.x;
    const int lane = tid & 31;
    const int wrp  = tid >> 5;
    const int bid  = blockIdx.x;

    // -------- schedule-order role mapping --------
    int role_gather, gt = 0, tile = 0;
    if (bid < G0) { role_gather = 1; gt = bid; }
    else if (bid < G0 + D0) { role_gather = 0; tile = bid - G0; }         // deg0 gemm
    else {
        int r = bid - (G0 + D0);
        if (r < 13664) {
            if ((r & 1) == 0) { role_gather = 1; gt = G0 + (r >> 1); }
            else              { role_gather = 0; tile = D0 + (r >> 1); }
        } else { role_gather = 0; tile = D0 + 6832 + (r - 13664); }
    }

    if (role_gather) {
        // -------- gather role: one rel tile -> scratch images --------
        const int cnt1[10] = {50000,100000,150000,100000,50000,5000,5000,5000,5000,5000};
        const int tls1[10] = {782,1563,2344,1563,782,79,79,79,79,79};
        int sgi = 0, btile = gt;
        while (btile >= tls1[sgi]) { btile -= tls1[sgi]; ++sgi; }
        const int deg  = sgi + 1;
        const int rows = min(MTILE, cnt1[sgi] - btile * MTILE);
        unsigned char* dstHi = g_RelHi + (size_t)gt * 16384;
        unsigned char* dstLo = g_RelLo + (size_t)gt * 16384;
        const int* adjp = adj.p[deg - 1] + (size_t)(btile * MTILE) * deg;
        switch (deg) {
            case 1:  gmean<1 >(af, adjp, dstHi, dstLo, rows, wrp, lane); break;
            case 2:  gmean<2 >(af, adjp, dstHi, dstLo, rows, wrp, lane); break;
            case 3:  gmean<3 >(af, adjp, dstHi, dstLo, rows, wrp, lane); break;
            case 4:  gmean<4 >(af, adjp, dstHi, dstLo, rows, wrp, lane); break;
            case 5:  gmean<5 >(af, adjp, dstHi, dstLo, rows, wrp, lane); break;
            case 6:  gmean<6 >(af, adjp, dstHi, dstLo, rows, wrp, lane); break;
            case 7:  gmean<7 >(af, adjp, dstHi, dstLo, rows, wrp, lane); break;
            case 8:  gmean<8 >(af, adjp, dstHi, dstLo, rows, wrp, lane); break;
            case 9:  gmean<9 >(af, adjp, dstHi, dstLo, rows, wrp, lane); break;
            default: gmean<10>(af, adjp, dstHi, dstLo, rows, wrp, lane); break;
        }
        __syncthreads();
        if (tid == 0) { __threadfence(); atomicExch(&g_done[gt], 1); }
        return;
    }

    // -------- gemm role --------
    extern __shared__ unsigned char dynsmem[];
    uint32_t base0 = smem_u32(dynsmem);
    uint32_t Abase = (base0 + 1023) & ~1023u;   // Ah 32KB + Al 32KB
    uint32_t Bbase = Abase + 65536;             // 2 x 16KB
    unsigned char* Ap = dynsmem + (Abase - base0);

    const int cnt[11] = {25000,50000,100000,150000,100000,50000,5000,5000,5000,5000,5000};
    const int off[11] = {0,25000,75000,175000,325000,425000,475000,480000,485000,490000,495000};

    int seg = 0, btile = tile;
    while (true) {
        int nt = (cnt[seg] + MTILE - 1) / MTILE;
        if (btile < nt) break;
        btile -= nt;
        ++seg;
    }
    const int deg  = seg;
    const int row0 = off[seg] + btile * MTILE;
    const int rows = min(MTILE, cnt[seg] - btile * MTILE);
    const int c0   = (deg == 0) ? 4 : 0;
    const int nch  = 8 - c0;
    const int rel  = tile - D0;                 // valid when deg>0

    // first B chunk cp.async (independent of rel readiness)
    {
        const unsigned char* sh = g_Wh[seg][c0];
        const unsigned char* sl = g_Wl[seg][c0];
        cpasync16(Bbase + tid * 16,               sh + tid * 16);
        cpasync16(Bbase + 4096 + tid * 16,        sh + 4096 + tid * 16);
        cpasync16(Bbase + 8192 + tid * 16,        sl + tid * 16);
        cpasync16(Bbase + 8192 + 4096 + tid * 16, sl + 4096 + tid * 16);
    }

    if (deg > 0) {
        // wait for producer (usually already done: ~4-wave margin)
        if (tid == 0) {
            while (atomicAdd(&g_done[rel], 0) == 0) __nanosleep(128);
            __threadfence();
        }
        __syncthreads();
        const unsigned char* srcH = g_RelHi + (size_t)rel * 16384;
        const unsigned char* srcL = g_RelLo + (size_t)rel * 16384;
        #pragma unroll
        for (int r = 0; r < 4; ++r) {
            int e = tid + r * 256;
            uint32_t so = (uint32_t)((e >> 4) * 512 + (e & 15) * 16);
            cpasync16(Abase + so,         srcH + (size_t)e * 16);
            cpasync16(Abase + 32768 + so, srcL + (size_t)e * 16);
        }
    }
    CP_COMMIT();

    // self rows: streaming load + bf16 split + STS (k 128..255)
    {
        const int k0 = lane * 4;
        #pragma unroll 1
        for (int ii = 0; ii < 8; ii += 4) {
            float4 sv[4];
            #pragma unroll
            for (int u = 0; u < 4; ++u) {
                int m = wrp * 8 + ii + u;
                int ml = (m < rows) ? m : 0;
                sv[u] = *(const float4*)(af + (size_t)(row0 + ml) * 128 + k0);
            }
            #pragma unroll
            for (int u = 0; u < 4; ++u) {
                int m = wrp * 8 + ii + u;
                if (m >= rows) continue;
                int swz  = (m & 7) << 4;
                int offS = ((m * 512 + 256 + 8 * lane) ^ swz);
                float4 s = sv[u];
                float sh0 = __bfloat162float(__float2bfloat16(s.x));
                float sh1 = __bfloat162float(__float2bfloat16(s.y));
                float sh2 = __bfloat162float(__float2bfloat16(s.z));
                float sh3 = __bfloat162float(__float2bfloat16(s.w));
                *(unsigned long long*)(Ap + offS)         = pack4bf(s.x, s.y, s.z, s.w);
                *(unsigned long long*)(Ap + 32768 + offS) = pack4bf(s.x - sh0, s.y - sh1, s.z - sh2, s.w - sh3);
            }
        }
    }

    // warp tiling: 2 (M32) x 4 (N32)
    const int wm = wrp >> 2;
    const int wn = wrp & 3;
    const int arow0 = wm * 32 + (lane & 15);
    const int aswz  = (arow0 & 7) << 4;
    const int aLow  = (lane >> 4) << 4;
    const uint32_t aB0 = Abase + arow0 * 512;
    const uint32_t aB1 = aB0 + 16 * 512;
    const int bswz = (lane & 7) << 4;
    const int bn   = wn * 32 + 8 * (lane >> 4);
    const uint32_t bOff0 = (lane & 15) * 256 + (uint32_t)(((bn +  0) * 2) ^ bswz);
    const uint32_t bOff1 = (lane & 15) * 256 + (uint32_t)(((bn + 16) * 2) ^ bswz);

    float acc[2][4][4];
    #pragma unroll
    for (int a = 0; a < 2; ++a)
        #pragma unroll
        for (int b = 0; b < 4; ++b)
            #pragma unroll
            for (int v = 0; v < 4; ++v) acc[a][b][v] = 0.f;

    #pragma unroll 1
    for (int ci = 0; ci < nch; ++ci) {
        const int c = c0 + ci;
        const uint32_t bufo = (uint32_t)(ci & 1) * 16384;
        if (ci + 1 < nch) {
            const unsigned char* sh = g_Wh[seg][c + 1];
            const unsigned char* sl = g_Wl[seg][c + 1];
            uint32_t d = Bbase + (((ci + 1) & 1) * 16384);
            cpasync16(d + tid * 16,               sh + tid * 16);
            cpasync16(d + 4096 + tid * 16,        sh + 4096 + tid * 16);
            cpasync16(d + 8192 + tid * 16,        sl + tid * 16);
            cpasync16(d + 8192 + 4096 + tid * 16, sl + 4096 + tid * 16);
            CP_COMMIT();
            CP_WAIT1();
        } else {
            CP_WAIT0();
        }
        __syncthreads();

        #pragma unroll
        for (int klh = 0; klh < 2; ++klh) {
            const int kl = klh * 16;
            const int kg = c * 32 + kl;
            uint32_t ah0[4], ah1[4], al0[4], al1[4];
            const uint32_t ak = (uint32_t)((aLow + kg * 2) ^ aswz);
            ldsm4(ah0, aB0 + ak);
            ldsm4(ah1, aB1 + ak);
            ldsm4(al0, aB0 + 32768 + ak);
            ldsm4(al1, aB1 + 32768 + ak);
            #pragma unroll
            for (int p = 0; p < 2; ++p) {
                uint32_t bh[4], bl[4];
                uint32_t ba = Bbase + bufo + (uint32_t)(kl * 256) + (p ? bOff1 : bOff0);
                ldsm4t(bh, ba);
                ldsm4t(bl, ba + 8192);
                const int n0 = 2 * p, n1 = 2 * p + 1;
                mma16816(acc[0][n0], ah0, bh[0], bh[1]);
                mma16816(acc[0][n1], ah0, bh[2], bh[3]);
                mma16816(acc[1][n0], ah1, bh[0], bh[1]);
                mma16816(acc[1][n1], ah1, bh[2], bh[3]);
                mma16816(acc[0][n0], al0, bh[0], bh[1]);
                mma16816(acc[0][n1], al0, bh[2], bh[3]);
                mma16816(acc[1][n0], al1, bh[0], bh[1]);
                mma16816(acc[1][n1], al1, bh[2], bh[3]);
                mma16816(acc[0][n0], ah0, bl[0], bl[1]);
                mma16816(acc[0][n1], ah0, bl[2], bl[3]);
                mma16816(acc[1][n0], ah1, bl[0], bl[1]);
                mma16816(acc[1][n1], ah1, bl[2], bl[3]);
            }
        }
        __syncthreads();
    }

    // epilogue: bias + ReLU + store
    const int colb = wn * 32 + 2 * (lane & 3);
    #pragma unroll
    for (int mt = 0; mt < 2; ++mt) {
        const int rbase = wm * 32 + mt * 16 + (lane >> 2);
        #pragma unroll
        for (int h = 0; h < 2; ++h) {
            const int m = rbase + h * 8;
            if (m < rows) {
                float* orow = out + (size_t)(row0 + m) * 128;
                #pragma unroll
                for (int nt = 0; nt < 4; ++nt) {
                    const int col = colb + nt * 8;
                    float2 b2 = *(const float2*)&g_bias[seg][col];
                    float2 o;
                    o.x = fmaxf(acc[mt][nt][h * 2 + 0] + b2.x, 0.f);
                    o.y = fmaxf(acc[mt][nt][h * 2 + 1] + b2.y, 0.f);
                    *(float2*)(orow + col) = o;
                }
            }
        }
    }
}

extern "C" void kernel_launch(void* const* d_in, const int* in_sizes, int n_in,
                              void* d_out, int out_size)
{
    const float* af = (const float*)d_in[0];
    AdjPtrs adj;
    for (int i = 0; i < 10; ++i) adj.p[i] = (const int*)d_in[2 + i];
    const float* W0    = (const float*)d_in[12];
    const float* b0    = (const float*)d_in[13];
    const float* Wrel  = (const float*)d_in[14];
    const float* brel  = (const float*)d_in[15];
    const float* Wself = (const float*)d_in[16];
    const float* bself = (const float*)d_in[17];
    float* out = (float*)d_out;

    prep_weights<<<(11 * 256 * 128 + 255) / 256, 256>>>(W0, b0, Wrel, brel, Wself, bself);
    reset_done<<<(NREL + 255) / 256, 256>>>();

    size_t shmem = 65536 + 32768 + 1024;   // A(64K) + B(32K) + align slack
    cudaFuncSetAttribute(graphconv_mix,
                         cudaFuncAttributeMaxDynamicSharedMemorySize, (int)shmem);
    graphconv_mix<<<NTOTAL, 256, shmem>>>(af, adj, out);
}

// round 12
// speedup vs baseline: 1.2057x; 1.2057x over previous
#include <cuda_runtime.h>
#include <cuda_bf16.h>
#include <cstdint>

#define MTILE 64

struct AdjPtrs { const int* p[10]; };

// Pre-split, pre-swizzled weights: [seg][kchunk(32k)][8KB] bf16, plus combined bias.
__device__ __align__(1024) unsigned char g_Wh[11][8][8192];
__device__ __align__(1024) unsigned char g_Wl[11][8][8192];
__device__ float g_bias[11][128];

__device__ __forceinline__ uint32_t smem_u32(const void* p) {
    uint32_t a;
    asm("{ .reg .u64 t; cvta.to.shared.u64 t, %1; cvt.u32.u64 %0, t; }" : "=r"(a) : "l"(p));
    return a;
}
__device__ __forceinline__ void ldsm4(uint32_t* r, uint32_t a) {
    asm volatile("ldmatrix.sync.aligned.m8n8.x4.shared.b16 {%0,%1,%2,%3}, [%4];"
        : "=r"(r[0]), "=r"(r[1]), "=r"(r[2]), "=r"(r[3]) : "r"(a));
}
__device__ __forceinline__ void ldsm4t(uint32_t* r, uint32_t a) {
    asm volatile("ldmatrix.sync.aligned.m8n8.x4.trans.shared.b16 {%0,%1,%2,%3}, [%4];"
        : "=r"(r[0]), "=r"(r[1]), "=r"(r[2]), "=r"(r[3]) : "r"(a));
}
__device__ __forceinline__ void mma16816(float* c, const uint32_t* a, uint32_t b0, uint32_t b1) {
    asm volatile("mma.sync.aligned.m16n8k16.row.col.f32.bf16.bf16.f32 "
        "{%0,%1,%2,%3}, {%4,%5,%6,%7}, {%8,%9}, {%0,%1,%2,%3};"
        : "+f"(c[0]), "+f"(c[1]), "+f"(c[2]), "+f"(c[3])
        : "r"(a[0]), "r"(a[1]), "r"(a[2]), "r"(a[3]), "r"(b0), "r"(b1));
}
__device__ __forceinline__ void cpasync16(uint32_t dst, const void* src) {
    asm volatile("cp.async.cg.shared.global [%0], [%1], 16;" :: "r"(dst), "l"(src) : "memory");
}
#define CP_COMMIT() asm volatile("cp.async.commit_group;" ::: "memory")
#define CP_WAIT1()  asm volatile("cp.async.wait_group 1;" ::: "memory")
#define CP_WAIT0()  asm volatile("cp.async.wait_group 0;" ::: "memory")

__device__ __forceinline__ unsigned long long pack4bf(float a0, float a1, float a2, float a3) {
    __nv_bfloat162 p0 = __floats2bfloat162_rn(a0, a1);
    __nv_bfloat162 p1 = __floats2bfloat162_rn(a2, a3);
    unsigned int u0 = *(unsigned int*)&p0;
    unsigned int u1 = *(unsigned int*)&p1;
    return (unsigned long long)u0 | ((unsigned long long)u1 << 32);
}

// ---------------- weight prep: fp32 -> pre-swizzled bf16 hi/lo chunks ----------------
__global__ void prep_weights(const float* __restrict__ W0,   const float* __restrict__ b0,
                             const float* __restrict__ Wrel, const float* __restrict__ brel,
                             const float* __restrict__ Wself,const float* __restrict__ bself)
{
    int idx = blockIdx.x * blockDim.x + threadIdx.x;
    if (idx >= 11 * 256 * 128) return;
    int n = idx & 127;
    int k = (idx >> 7) & 255;
    int s = idx >> 15;
    float w;
    if (s == 0) w = (k < 128) ? 0.f : W0[(size_t)(k - 128) * 128 + n];
    else        w = (k < 128) ? Wrel[((size_t)(s - 1) * 128 + k) * 128 + n]
                              : Wself[((size_t)(s - 1) * 128 + (k - 128)) * 128 + n];
    __nv_bfloat16 hi = __float2bfloat16(w);
    __nv_bfloat16 lo = __float2bfloat16(w - __bfloat162float(hi));
    int b = (((k & 31) * 256) + n * 2) ^ ((k & 7) << 4);
    *(__nv_bfloat16*)(g_Wh[s][k >> 5] + b) = hi;
    *(__nv_bfloat16*)(g_Wl[s][k >> 5] + b) = lo;
    if (k == 0) g_bias[s][n] = (s == 0) ? b0[n] : brel[(s - 1) * 128 + n] + bself[(s - 1) * 128 + n];
}

// ---------------- rel gather into halved A (hi @0, lo @16KB; 256B rows) -------------
template<int DEG>
__device__ __forceinline__ void gather_rel_half(const float* __restrict__ af,
                                                const int* __restrict__ adjp,
                                                unsigned char* __restrict__ Ap,
                                                int rows, int wrp, int lane)
{
    const int k0 = lane * 4;
    constexpr int UN = (DEG <= 2) ? 4 : (DEG <= 5 ? 2 : 1);
    #pragma unroll 1
    for (int ii = 0; ii < 8; ii += UN) {
        float4 nb[UN][DEG];
        #pragma unroll
        for (int u = 0; u < UN; ++u) {
            int m = wrp * 8 + ii + u;
            int ml = (m < rows) ? m : 0;
            int idxs[DEG];
            const int* ar = adjp + (size_t)ml * DEG;
            #pragma unroll
            for (int j = 0; j < DEG; ++j) idxs[j] = __ldg(ar + j);
            #pragma unroll
            for (int j = 0; j < DEG; ++j)
                nb[u][j] = *(const float4*)(af + (size_t)idxs[j] * 128 + k0);
        }
        #pragma unroll
        for (int u = 0; u < UN; ++u) {
            int m = wrp * 8 + ii + u;
            if (m >= rows) continue;
            float4 r4 = make_float4(0.f, 0.f, 0.f, 0.f);
            #pragma unroll
            for (int j = 0; j < DEG; ++j) {
                r4.x += nb[u][j].x; r4.y += nb[u][j].y;
                r4.z += nb[u][j].z; r4.w += nb[u][j].w;
            }
            constexpr float inv = 1.0f / (float)DEG;
            r4.x *= inv; r4.y *= inv; r4.z *= inv; r4.w *= inv;
            float h0 = __bfloat162float(__float2bfloat16(r4.x));
            float h1 = __bfloat162float(__float2bfloat16(r4.y));
            float h2 = __bfloat162float(__float2bfloat16(r4.z));
            float h3 = __bfloat162float(__float2bfloat16(r4.w));
            int off = ((m * 256 + 8 * lane) ^ ((m & 7) << 4));
            *(unsigned long long*)(Ap + off)         = pack4bf(r4.x, r4.y, r4.z, r4.w);
            *(unsigned long long*)(Ap + 16384 + off) = pack4bf(r4.x - h0, r4.y - h1, r4.z - h2, r4.w - h3);
        }
    }
}

// ---------------- self rows into halved A (streaming, coalesced) --------------------
__device__ __forceinline__ void load_self_half(const float* __restrict__ af,
                                               unsigned char* __restrict__ Ap,
                                               int row0, int rows, int wrp, int lane)
{
    const int k0 = lane * 4;
    #pragma unroll 1
    for (int ii = 0; ii < 8; ii += 4) {
        float4 sv[4];
        #pragma unroll
        for (int u = 0; u < 4; ++u) {
            int m = wrp * 8 + ii + u;
            int ml = (m < rows) ? m : 0;
            sv[u] = *(const float4*)(af + (size_t)(row0 + ml) * 128 + k0);
        }
        #pragma unroll
        for (int u = 0; u < 4; ++u) {
            int m = wrp * 8 + ii + u;
            if (m >= rows) continue;
            float4 s = sv[u];
            float h0 = __bfloat162float(__float2bfloat16(s.x));
            float h1 = __bfloat162float(__float2bfloat16(s.y));
            float h2 = __bfloat162float(__float2bfloat16(s.z));
            float h3 = __bfloat162float(__float2bfloat16(s.w));
            int off = ((m * 256 + 8 * lane) ^ ((m & 7) << 4));
            *(unsigned long long*)(Ap + off)         = pack4bf(s.x, s.y, s.z, s.w);
            *(unsigned long long*)(Ap + 16384 + off) = pack4bf(s.x - h0, s.y - h1, s.z - h2, s.w - h3);
        }
    }
}

// ---------------- main fused kernel: halved A, 3 CTAs/SM ----------------------------
__global__ __launch_bounds__(256, 3)
void graphconv_hmma(const float* __restrict__ af, AdjPtrs adj, float* __restrict__ out)
{
    extern __shared__ unsigned char dynsmem[];
    uint32_t base0 = smem_u32(dynsmem);
    uint32_t Abase = (base0 + 1023) & ~1023u;   // A: hi 16KB + lo 16KB
    uint32_t Bbase = Abase + 32768;             // B: 2 x 16KB (hi 8KB + lo 8KB per buf)
    unsigned char* Ap = dynsmem + (Abase - base0);

    const int cnt[11] = {25000,50000,100000,150000,100000,50000,5000,5000,5000,5000,5000};
    const int off[11] = {0,25000,75000,175000,325000,425000,475000,480000,485000,490000,495000};

    int seg = 0, btile = blockIdx.x;
    while (true) {
        int nt = (cnt[seg] + MTILE - 1) / MTILE;
        if (btile < nt) break;
        btile -= nt;
        ++seg;
    }
    const int deg  = seg;
    const int row0 = off[seg] + btile * MTILE;
    const int rows = min(MTILE, cnt[seg] - btile * MTILE);

    const int tid  = threadIdx.x;
    const int lane = tid & 31;
    const int wrp  = tid >> 5;

    const int c0  = (deg == 0) ? 4 : 0;
    const int nch = 8 - c0;

    // -------- prefetch first weight chunk (overlaps A fill) --------
    {
        const unsigned char* sh = g_Wh[seg][c0];
        const unsigned char* sl = g_Wl[seg][c0];
        cpasync16(Bbase + tid * 16,               sh + tid * 16);
        cpasync16(Bbase + 4096 + tid * 16,        sh + 4096 + tid * 16);
        cpasync16(Bbase + 8192 + tid * 16,        sl + tid * 16);
        cpasync16(Bbase + 8192 + 4096 + tid * 16, sl + 4096 + tid * 16);
        CP_COMMIT();
    }

    // -------- fill A with first half --------
    if (deg > 0) {
        const int* adjp = adj.p[deg - 1] + (size_t)(btile * MTILE) * deg;
        switch (deg) {
            case 1:  gather_rel_half<1 >(af, adjp, Ap, rows, wrp, lane); break;
            case 2:  gather_rel_half<2 >(af, adjp, Ap, rows, wrp, lane); break;
            case 3:  gather_rel_half<3 >(af, adjp, Ap, rows, wrp, lane); break;
            case 4:  gather_rel_half<4 >(af, adjp, Ap, rows, wrp, lane); break;
            case 5:  gather_rel_half<5 >(af, adjp, Ap, rows, wrp, lane); break;
            case 6:  gather_rel_half<6 >(af, adjp, Ap, rows, wrp, lane); break;
            case 7:  gather_rel_half<7 >(af, adjp, Ap, rows, wrp, lane); break;
            case 8:  gather_rel_half<8 >(af, adjp, Ap, rows, wrp, lane); break;
            case 9:  gather_rel_half<9 >(af, adjp, Ap, rows, wrp, lane); break;
            default: gather_rel_half<10>(af, adjp, Ap, rows, wrp, lane); break;
        }
    } else {
        load_self_half(af, Ap, row0, rows, wrp, lane);
    }
    __syncthreads();

    // -------- warp tiling: 2 (M32) x 4 (N32) --------
    const int wm = wrp >> 2;
    const int wn = wrp & 3;

    const int arow0 = wm * 32 + (lane & 15);
    const int aswz  = (arow0 & 7) << 4;
    const int aLow  = (lane >> 4) << 4;
    const uint32_t aB0 = Abase + arow0 * 256;
    const uint32_t aB1 = aB0 + 16 * 256;

    const int bswz = (lane & 7) << 4;
    const int bn   = wn * 32 + 8 * (lane >> 4);
    const uint32_t bOff0 = (lane & 15) * 256 + (uint32_t)(((bn +  0) * 2) ^ bswz);
    const uint32_t bOff1 = (lane & 15) * 256 + (uint32_t)(((bn + 16) * 2) ^ bswz);

    float acc[2][4][4];
    #pragma unroll
    for (int a = 0; a < 2; ++a)
        #pragma unroll
        for (int b = 0; b < 4; ++b)
            #pragma unroll
            for (int v = 0; v < 4; ++v) acc[a][b][v] = 0.f;

    #pragma unroll 1
    for (int ci = 0; ci < nch; ++ci) {
        const int c = c0 + ci;

        // refill A with self half between chunk 3 and 4 (deg>0 path)
        if (deg > 0 && ci == 4) {
            load_self_half(af, Ap, row0, rows, wrp, lane);   // prev loop-end sync covers A reads
            __syncthreads();
        }

        const uint32_t bufo = (uint32_t)(ci & 1) * 16384;
        if (ci + 1 < nch) {
            const unsigned char* sh = g_Wh[seg][c + 1];
            const unsigned char* sl = g_Wl[seg][c + 1];
            uint32_t d = Bbase + (((ci + 1) & 1) * 16384);
            cpasync16(d + tid * 16,               sh + tid * 16);
            cpasync16(d + 4096 + tid * 16,        sh + 4096 + tid * 16);
            cpasync16(d + 8192 + tid * 16,        sl + tid * 16);
            cpasync16(d + 8192 + 4096 + tid * 16, sl + 4096 + tid * 16);
            CP_COMMIT();
            CP_WAIT1();
        } else {
            CP_WAIT0();
        }
        __syncthreads();

        const int klb = (c & 3) * 32;   // k position within current A half
        #pragma unroll
        for (int klh = 0; klh < 2; ++klh) {
            const int kl = klh * 16;
            uint32_t ah0[4], ah1[4], al0[4], al1[4];
            const uint32_t ak = (uint32_t)((aLow + (klb + kl) * 2) ^ aswz);
            ldsm4(ah0, aB0 + ak);
            ldsm4(ah1, aB1 + ak);
            ldsm4(al0, aB0 + 16384 + ak);
            ldsm4(al1, aB1 + 16384 + ak);
            #pragma unroll
            for (int p = 0; p < 2; ++p) {
                uint32_t bh[4], bl[4];
                uint32_t ba = Bbase + bufo + (uint32_t)(kl * 256) + (p ? bOff1 : bOff0);
                ldsm4t(bh, ba);
                ldsm4t(bl, ba + 8192);
                const int n0 = 2 * p, n1 = 2 * p + 1;
                mma16816(acc[0][n0], ah0, bh[0], bh[1]);
                mma16816(acc[0][n1], ah0, bh[2], bh[3]);
                mma16816(acc[1][n0], ah1, bh[0], bh[1]);
                mma16816(acc[1][n1], ah1, bh[2], bh[3]);
                mma16816(acc[0][n0], al0, bh[0], bh[1]);
                mma16816(acc[0][n1], al0, bh[2], bh[3]);
                mma16816(acc[1][n0], al1, bh[0], bh[1]);
                mma16816(acc[1][n1], al1, bh[2], bh[3]);
                mma16816(acc[0][n0], ah0, bl[0], bl[1]);
                mma16816(acc[0][n1], ah0, bl[2], bl[3]);
                mma16816(acc[1][n0], ah1, bl[0], bl[1]);
                mma16816(acc[1][n1], ah1, bl[2], bl[3]);
            }
        }
        __syncthreads();
    }

    // -------- epilogue: bias + ReLU + store --------
    const int colb = wn * 32 + 2 * (lane & 3);
    #pragma unroll
    for (int mt = 0; mt < 2; ++mt) {
        const int rbase = wm * 32 + mt * 16 + (lane >> 2);
        #pragma unroll
        for (int h = 0; h < 2; ++h) {
            const int m = rbase + h * 8;
            if (m < rows) {
                float* orow = out + (size_t)(row0 + m) * 128;
                #pragma unroll
                for (int nt = 0; nt < 4; ++nt) {
                    const int col = colb + nt * 8;
                    float2 b2 = *(const float2*)&g_bias[seg][col];
                    float2 o;
                    o.x = fmaxf(acc[mt][nt][h * 2 + 0] + b2.x, 0.f);
                    o.y = fmaxf(acc[mt][nt][h * 2 + 1] + b2.y, 0.f);
                    *(float2*)(orow + col) = o;
                }
            }
        }
    }
}

extern "C" void kernel_launch(void* const* d_in, const int* in_sizes, int n_in,
                              void* d_out, int out_size)
{
    const float* af = (const float*)d_in[0];
    AdjPtrs adj;
    for (int i = 0; i < 10; ++i) adj.p[i] = (const int*)d_in[2 + i];
    const float* W0    = (const float*)d_in[12];
    const float* b0    = (const float*)d_in[13];
    const float* Wrel  = (const float*)d_in[14];
    const float* brel  = (const float*)d_in[15];
    const float* Wself = (const float*)d_in[16];
    const float* bself = (const float*)d_in[17];
    float* out = (float*)d_out;

    prep_weights<<<(11 * 256 * 128 + 255) / 256, 256>>>(W0, b0, Wrel, brel, Wself, bself);

    static const int cnt[11] = {25000,50000,100000,150000,100000,50000,5000,5000,5000,5000,5000};
    int tiles = 0;
    for (int i = 0; i < 11; ++i) tiles += (cnt[i] + MTILE - 1) / MTILE;  // 7820

    size_t shmem = 32768 + 32768 + 1024;   // A(32K) + B(32K) + align slack
    cudaFuncSetAttribute(graphconv_hmma,
                         cudaFuncAttributeMaxDynamicSharedMemorySize, (int)shmem);
    graphconv_hmma<<<tiles, 256, shmem>>>(af, adj, out);
}

// round 13
// speedup vs baseline: 1.2764x; 1.0586x over previous
#include <cuda_runtime.h>
#include <cuda_bf16.h>
#include <cstdint>

#define MTILE 64

struct AdjPtrs { const int* p[10]; };

// Pre-split, pre-swizzled weights: [seg][kchunk(32k)][8KB] bf16, plus combined bias.
__device__ __align__(1024) unsigned char g_Wh[11][8][8192];
__device__ __align__(1024) unsigned char g_Wl[11][8][8192];
__device__ float g_bias[11][128];

__device__ __forceinline__ uint32_t smem_u32(const void* p) {
    uint32_t a;
    asm("{ .reg .u64 t; cvta.to.shared.u64 t, %1; cvt.u32.u64 %0, t; }" : "=r"(a) : "l"(p));
    return a;
}
__device__ __forceinline__ void ldsm4(uint32_t* r, uint32_t a) {
    asm volatile("ldmatrix.sync.aligned.m8n8.x4.shared.b16 {%0,%1,%2,%3}, [%4];"
        : "=r"(r[0]), "=r"(r[1]), "=r"(r[2]), "=r"(r[3]) : "r"(a));
}
__device__ __forceinline__ void ldsm4t(uint32_t* r, uint32_t a) {
    asm volatile("ldmatrix.sync.aligned.m8n8.x4.trans.shared.b16 {%0,%1,%2,%3}, [%4];"
        : "=r"(r[0]), "=r"(r[1]), "=r"(r[2]), "=r"(r[3]) : "r"(a));
}
__device__ __forceinline__ void mma16816(float* c, const uint32_t* a, uint32_t b0, uint32_t b1) {
    asm volatile("mma.sync.aligned.m16n8k16.row.col.f32.bf16.bf16.f32 "
        "{%0,%1,%2,%3}, {%4,%5,%6,%7}, {%8,%9}, {%0,%1,%2,%3};"
        : "+f"(c[0]), "+f"(c[1]), "+f"(c[2]), "+f"(c[3])
        : "r"(a[0]), "r"(a[1]), "r"(a[2]), "r"(a[3]), "r"(b0), "r"(b1));
}
__device__ __forceinline__ void cpasync16(uint32_t dst, const void* src) {
    asm volatile("cp.async.cg.shared.global [%0], [%1], 16;" :: "r"(dst), "l"(src) : "memory");
}
#define CP_COMMIT() asm volatile("cp.async.commit_group;" ::: "memory")
#define CP_WAIT1()  asm volatile("cp.async.wait_group 1;" ::: "memory")
#define CP_WAIT0()  asm volatile("cp.async.wait_group 0;" ::: "memory")

__device__ __forceinline__ unsigned long long pack4bf(float a0, float a1, float a2, float a3) {
    __nv_bfloat162 p0 = __floats2bfloat162_rn(a0, a1);
    __nv_bfloat162 p1 = __floats2bfloat162_rn(a2, a3);
    unsigned int u0 = *(unsigned int*)&p0;
    unsigned int u1 = *(unsigned int*)&p1;
    return (unsigned long long)u0 | ((unsigned long long)u1 << 32);
}

// ---------------- weight prep: fp32 -> pre-swizzled bf16 hi/lo chunks ----------------
__global__ void prep_weights(const float* __restrict__ W0,   const float* __restrict__ b0,
                             const float* __restrict__ Wrel, const float* __restrict__ brel,
                             const float* __restrict__ Wself,const float* __restrict__ bself)
{
    int idx = blockIdx.x * blockDim.x + threadIdx.x;
    if (idx >= 11 * 256 * 128) return;
    int n = idx & 127;
    int k = (idx >> 7) & 255;
    int s = idx >> 15;
    float w;
    if (s == 0) w = (k < 128) ? 0.f : W0[(size_t)(k - 128) * 128 + n];
    else        w = (k < 128) ? Wrel[((size_t)(s - 1) * 128 + k) * 128 + n]
                              : Wself[((size_t)(s - 1) * 128 + (k - 128)) * 128 + n];
    __nv_bfloat16 hi = __float2bfloat16(w);
    __nv_bfloat16 lo = __float2bfloat16(w - __bfloat162float(hi));
    int b = (((k & 31) * 256) + n * 2) ^ ((k & 7) << 4);
    *(__nv_bfloat16*)(g_Wh[s][k >> 5] + b) = hi;
    *(__nv_bfloat16*)(g_Wl[s][k >> 5] + b) = lo;
    if (k == 0) g_bias[s][n] = (s == 0) ? b0[n] : brel[(s - 1) * 128 + n] + bself[(s - 1) * 128 + n];
}

// ---------------- rel gather: warp-cooperative idx prefetch + deep row batching -----
template<int DEG>
__device__ __forceinline__ void gather_rel_half(const float* __restrict__ af,
                                                const int* __restrict__ adjp,
                                                unsigned char* __restrict__ Ap,
                                                int rows, int wrp, int lane)
{
    const int k0 = lane * 4;
    constexpr int NI = 8 * DEG;              // indices per warp (<= 80)
    constexpr int NR = (NI + 31) / 32;       // regs per lane (1..3)

    // one coalesced batch: lane l holds flat indices l, l+32, l+64
    int ridx[NR];
    const int liveRows = min(max(rows - wrp * 8, 0), 8);
    const int nlive = liveRows * DEG;
    const int* base = adjp + (wrp * 8) * DEG;
    #pragma unroll
    for (int r = 0; r < NR; ++r) {
        int e = lane + r * 32;
        ridx[r] = (e < nlive) ? __ldg(base + e) : 0;
    }

    constexpr int UN = (DEG <= 1) ? 8 : (DEG <= 3) ? 4 : (DEG <= 5) ? 2 : 1;
    #pragma unroll
    for (int ii = 0; ii < 8; ii += UN) {
        float4 nb[UN][DEG];
        #pragma unroll
        for (int u = 0; u < UN; ++u) {
            #pragma unroll
            for (int j = 0; j < DEG; ++j) {
                constexpr unsigned FULL = 0xffffffffu;
                const int flat = (ii + u) * DEG + j;          // compile-time
                int idx = __shfl_sync(FULL, ridx[flat >> 5], flat & 31);
                nb[u][j] = *(const float4*)(af + (size_t)idx * 128 + k0);
            }
        }
        #pragma unroll
        for (int u = 0; u < UN; ++u) {
            int m = wrp * 8 + ii + u;
            if (m >= rows) continue;
            float4 r4 = make_float4(0.f, 0.f, 0.f, 0.f);
            #pragma unroll
            for (int j = 0; j < DEG; ++j) {
                r4.x += nb[u][j].x; r4.y += nb[u][j].y;
                r4.z += nb[u][j].z; r4.w += nb[u][j].w;
            }
            constexpr float inv = 1.0f / (float)DEG;
            r4.x *= inv; r4.y *= inv; r4.z *= inv; r4.w *= inv;
            float h0 = __bfloat162float(__float2bfloat16(r4.x));
            float h1 = __bfloat162float(__float2bfloat16(r4.y));
            float h2 = __bfloat162float(__float2bfloat16(r4.z));
            float h3 = __bfloat162float(__float2bfloat16(r4.w));
            int off = ((m * 256 + 8 * lane) ^ ((m & 7) << 4));
            *(unsigned long long*)(Ap + off)         = pack4bf(r4.x, r4.y, r4.z, r4.w);
            *(unsigned long long*)(Ap + 16384 + off) = pack4bf(r4.x - h0, r4.y - h1, r4.z - h2, r4.w - h3);
        }
    }
}

// ---------------- self rows into halved A (streaming, coalesced) --------------------
__device__ __forceinline__ void load_self_half(const float* __restrict__ af,
                                               unsigned char* __restrict__ Ap,
                                               int row0, int rows, int wrp, int lane)
{
    const int k0 = lane * 4;
    #pragma unroll 1
    for (int ii = 0; ii < 8; ii += 4) {
        float4 sv[4];
        #pragma unroll
        for (int u = 0; u < 4; ++u) {
            int m = wrp * 8 + ii + u;
            int ml = (m < rows) ? m : 0;
            sv[u] = *(const float4*)(af + (size_t)(row0 + ml) * 128 + k0);
        }
        #pragma unroll
        for (int u = 0; u < 4; ++u) {
            int m = wrp * 8 + ii + u;
            if (m >= rows) continue;
            float4 s = sv[u];
            float h0 = __bfloat162float(__float2bfloat16(s.x));
            float h1 = __bfloat162float(__float2bfloat16(s.y));
            float h2 = __bfloat162float(__float2bfloat16(s.z));
            float h3 = __bfloat162float(__float2bfloat16(s.w));
            int off = ((m * 256 + 8 * lane) ^ ((m & 7) << 4));
            *(unsigned long long*)(Ap + off)         = pack4bf(s.x, s.y, s.z, s.w);
            *(unsigned long long*)(Ap + 16384 + off) = pack4bf(s.x - h0, s.y - h1, s.z - h2, s.w - h3);
        }
    }
}

// ---------------- main fused kernel: halved A, 3 CTAs/SM ----------------------------
__global__ __launch_bounds__(256, 3)
void graphconv_hmma(const float* __restrict__ af, AdjPtrs adj, float* __restrict__ out)
{
    extern __shared__ unsigned char dynsmem[];
    uint32_t base0 = smem_u32(dynsmem);
    uint32_t Abase = (base0 + 1023) & ~1023u;   // A: hi 16KB + lo 16KB
    uint32_t Bbase = Abase + 32768;             // B: 2 x 16KB (hi 8KB + lo 8KB per buf)
    unsigned char* Ap = dynsmem + (Abase - base0);

    const int cnt[11] = {25000,50000,100000,150000,100000,50000,5000,5000,5000,5000,5000};
    const int off[11] = {0,25000,75000,175000,325000,425000,475000,480000,485000,490000,495000};

    int seg = 0, btile = blockIdx.x;
    while (true) {
        int nt = (cnt[seg] + MTILE - 1) / MTILE;
        if (btile < nt) break;
        btile -= nt;
        ++seg;
    }
    const int deg  = seg;
    const int row0 = off[seg] + btile * MTILE;
    const int rows = min(MTILE, cnt[seg] - btile * MTILE);

    const int tid  = threadIdx.x;
    const int lane = tid & 31;
    const int wrp  = tid >> 5;

    const int c0  = (deg == 0) ? 4 : 0;
    const int nch = 8 - c0;

    // -------- prefetch first weight chunk (overlaps A fill) --------
    {
        const unsigned char* sh = g_Wh[seg][c0];
        const unsigned char* sl = g_Wl[seg][c0];
        cpasync16(Bbase + tid * 16,               sh + tid * 16);
        cpasync16(Bbase + 4096 + tid * 16,        sh + 4096 + tid * 16);
        cpasync16(Bbase + 8192 + tid * 16,        sl + tid * 16);
        cpasync16(Bbase + 8192 + 4096 + tid * 16, sl + 4096 + tid * 16);
        CP_COMMIT();
    }

    // -------- fill A with first half --------
    if (deg > 0) {
        const int* adjp = adj.p[deg - 1] + (size_t)(btile * MTILE) * deg;
        switch (deg) {
            case 1:  gather_rel_half<1 >(af, adjp, Ap, rows, wrp, lane); break;
            case 2:  gather_rel_half<2 >(af, adjp, Ap, rows, wrp, lane); break;
            case 3:  gather_rel_half<3 >(af, adjp, Ap, rows, wrp, lane); break;
            case 4:  gather_rel_half<4 >(af, adjp, Ap, rows, wrp, lane); break;
            case 5:  gather_rel_half<5 >(af, adjp, Ap, rows, wrp, lane); break;
            case 6:  gather_rel_half<6 >(af, adjp, Ap, rows, wrp, lane); break;
            case 7:  gather_rel_half<7 >(af, adjp, Ap, rows, wrp, lane); break;
            case 8:  gather_rel_half<8 >(af, adjp, Ap, rows, wrp, lane); break;
            case 9:  gather_rel_half<9 >(af, adjp, Ap, rows, wrp, lane); break;
            default: gather_rel_half<10>(af, adjp, Ap, rows, wrp, lane); break;
        }
    } else {
        load_self_half(af, Ap, row0, rows, wrp, lane);
    }
    __syncthreads();

    // -------- warp tiling: 2 (M32) x 4 (N32) --------
    const int wm = wrp >> 2;
    const int wn = wrp & 3;

    const int arow0 = wm * 32 + (lane & 15);
    const int aswz  = (arow0 & 7) << 4;
    const int aLow  = (lane >> 4) << 4;
    const uint32_t aB0 = Abase + arow0 * 256;
    const uint32_t aB1 = aB0 + 16 * 256;

    const int bswz = (lane & 7) << 4;
    const int bn   = wn * 32 + 8 * (lane >> 4);
    const uint32_t bOff0 = (lane & 15) * 256 + (uint32_t)(((bn +  0) * 2) ^ bswz);
    const uint32_t bOff1 = (lane & 15) * 256 + (uint32_t)(((bn + 16) * 2) ^ bswz);

    float acc[2][4][4];
    #pragma unroll
    for (int a = 0; a < 2; ++a)
        #pragma unroll
        for (int b = 0; b < 4; ++b)
            #pragma unroll
            for (int v = 0; v < 4; ++v) acc[a][b][v] = 0.f;

    #pragma unroll 1
    for (int ci = 0; ci < nch; ++ci) {
        const int c = c0 + ci;

        // refill A with self half between chunk 3 and 4 (deg>0 path)
        if (deg > 0 && ci == 4) {
            load_self_half(af, Ap, row0, rows, wrp, lane);   // prev loop-end sync covers A reads
            __syncthreads();
        }

        const uint32_t bufo = (uint32_t)(ci & 1) * 16384;
        if (ci + 1 < nch) {
            const unsigned char* sh = g_Wh[seg][c + 1];
            const unsigned char* sl = g_Wl[seg][c + 1];
            uint32_t d = Bbase + (((ci + 1) & 1) * 16384);
            cpasync16(d + tid * 16,               sh + tid * 16);
            cpasync16(d + 4096 + tid * 16,        sh + 4096 + tid * 16);
            cpasync16(d + 8192 + tid * 16,        sl + tid * 16);
            cpasync16(d + 8192 + 4096 + tid * 16, sl + 4096 + tid * 16);
            CP_COMMIT();
            CP_WAIT1();
        } else {
            CP_WAIT0();
        }
        __syncthreads();

        const int klb = (c & 3) * 32;   // k position within current A half
        #pragma unroll
        for (int klh = 0; klh < 2; ++klh) {
            const int kl = klh * 16;
            uint32_t ah0[4], ah1[4], al0[4], al1[4];
            const uint32_t ak = (uint32_t)((aLow + (klb + kl) * 2) ^ aswz);
            ldsm4(ah0, aB0 + ak);
            ldsm4(ah1, aB1 + ak);
            ldsm4(al0, aB0 + 16384 + ak);
            ldsm4(al1, aB1 + 16384 + ak);
            #pragma unroll
            for (int p = 0; p < 2; ++p) {
                uint32_t bh[4], bl[4];
                uint32_t ba = Bbase + bufo + (uint32_t)(kl * 256) + (p ? bOff1 : bOff0);
                ldsm4t(bh, ba);
                ldsm4t(bl, ba + 8192);
                const int n0 = 2 * p, n1 = 2 * p + 1;
                mma16816(acc[0][n0], ah0, bh[0], bh[1]);
                mma16816(acc[0][n1], ah0, bh[2], bh[3]);
                mma16816(acc[1][n0], ah1, bh[0], bh[1]);
                mma16816(acc[1][n1], ah1, bh[2], bh[3]);
                mma16816(acc[0][n0], al0, bh[0], bh[1]);
                mma16816(acc[0][n1], al0, bh[2], bh[3]);
                mma16816(acc[1][n0], al1, bh[0], bh[1]);
                mma16816(acc[1][n1], al1, bh[2], bh[3]);
                mma16816(acc[0][n0], ah0, bl[0], bl[1]);
                mma16816(acc[0][n1], ah0, bl[2], bl[3]);
                mma16816(acc[1][n0], ah1, bl[0], bl[1]);
                mma16816(acc[1][n1], ah1, bl[2], bl[3]);
            }
        }
        __syncthreads();
    }

    // -------- epilogue: bias + ReLU + store --------
    const int colb = wn * 32 + 2 * (lane & 3);
    #pragma unroll
    for (int mt = 0; mt < 2; ++mt) {
        const int rbase = wm * 32 + mt * 16 + (lane >> 2);
        #pragma unroll
        for (int h = 0; h < 2; ++h) {
            const int m = rbase + h * 8;
            if (m < rows) {
                float* orow = out + (size_t)(row0 + m) * 128;
                #pragma unroll
                for (int nt = 0; nt < 4; ++nt) {
                    const int col = colb + nt * 8;
                    float2 b2 = *(const float2*)&g_bias[seg][col];
                    float2 o;
                    o.x = fmaxf(acc[mt][nt][h * 2 + 0] + b2.x, 0.f);
                    o.y = fmaxf(acc[mt][nt][h * 2 + 1] + b2.y, 0.f);
                    *(float2*)(orow + col) = o;
                }
            }
        }
    }
}

extern "C" void kernel_launch(void* const* d_in, const int* in_sizes, int n_in,
                              void* d_out, int out_size)
{
    const float* af = (const float*)d_in[0];
    AdjPtrs adj;
    for (int i = 0; i < 10; ++i) adj.p[i] = (const int*)d_in[2 + i];
    const float* W0    = (const float*)d_in[12];
    const float* b0    = (const float*)d_in[13];
    const float* Wrel  = (const float*)d_in[14];
    const float* brel  = (const float*)d_in[15];
    const float* Wself = (const float*)d_in[16];
    const float* bself = (const float*)d_in[17];
    float* out = (float*)d_out;

    prep_weights<<<(11 * 256 * 128 + 255) / 256, 256>>>(W0, b0, Wrel, brel, Wself, bself);

    static const int cnt[11] = {25000,50000,100000,150000,100000,50000,5000,5000,5000,5000,5000};
    int tiles = 0;
    for (int i = 0; i < 11; ++i) tiles += (cnt[i] + MTILE - 1) / MTILE;  // 7820

    size_t shmem = 32768 + 32768 + 1024;   // A(32K) + B(32K) + align slack
    cudaFuncSetAttribute(graphconv_hmma,
                         cudaFuncAttributeMaxDynamicSharedMemorySize, (int)shmem);
    graphconv_hmma<<<tiles, 256, shmem>>>(af, adj, out);
}